// round 12
// baseline (speedup 1.0000x reference)
#include <cuda_runtime.h>

#define T   64
#define NN  4096
#define ST1 42   // lvl1 array row stride (40 rows used)

// Shared layout (float offsets).
#define O_LH1  0        // 40x42
#define O_HL1  1680
#define O_HH1  3360
#define O_LL2  5040     // 20x20, stored = logical+2
#define O_LH2  5440
#define O_HL2  5840
#define O_HH2  6240
#define O_LL3  6640     // 10x10, stored = logical+1
#define O_LH3  6740
#define O_HL3  6840
#define O_HH3  6940
#define O_CHH2 7040     // 16x16
#define O_CHH1 7296     // 32x32
#define O_REC2 8320     // 16x16
#define SMEM_FLOATS 8576

// Constant bank as float2 pairs (8B aligned for LDC.64):
//  slots 0..48  : (w7[i], w7[i])
//  slots 49..73 : (w5[i], w5[i])
//  floats 148-150: b7, b5, b3
//  floats 152-160: w3[0..8] scalar
__constant__ float2 c_w2[82];

#define CW_F   ((const float*)c_w2)
#define CB7    CW_F[148]
#define CB5    CW_F[149]
#define CB3    CW_F[150]
#define W3S(i) CW_F[152 + (i)]

typedef unsigned long long ull;

__device__ __forceinline__ ull pk2(float lo, float hi) {
    ull r; asm("mov.b64 %0, {%1,%2};" : "=l"(r) : "f"(lo), "f"(hi)); return r;
}
__device__ __forceinline__ void upk2(ull v, float& lo, float& hi) {
    asm("mov.b64 {%0,%1}, %2;" : "=f"(lo), "=f"(hi) : "l"(v));
}
__device__ __forceinline__ ull fma2(ull a, ull b, ull c) {
    ull d; asm("fma.rn.f32x2 %0, %1, %2, %3;" : "=l"(d) : "l"(a), "l"(b), "l"(c));
    return d;
}
__device__ __forceinline__ ull w7p(int i) {
    return reinterpret_cast<const ull*>(c_w2)[i];
}
__device__ __forceinline__ ull w5p(int i) {
    return reinterpret_cast<const ull*>(c_w2)[49 + i];
}

// Writes the packed weight bank DIRECTLY into constant memory storage.
__global__ void pack_weights(float* __restrict__ dst,
                             const float* __restrict__ w3, const float* __restrict__ b3,
                             const float* __restrict__ w5, const float* __restrict__ b5,
                             const float* __restrict__ w7, const float* __restrict__ b7)
{
    int t = threadIdx.x;
    float v = 0.f;
    if (t < 98)        v = w7[t >> 1];
    else if (t < 148)  v = w5[(t - 98) >> 1];
    else if (t == 148) v = b7[0];
    else if (t == 149) v = b5[0];
    else if (t == 150) v = b3[0];
    else if (t >= 152 && t < 161) v = w3[t - 152];
    if (t < 164) dst[t] = v;
}

__global__ __launch_bounds__(512, 4) void fused_wavelet_kernel(
    const float* __restrict__ x, float* __restrict__ out)
{
    __shared__ float s[SMEM_FLOATS];
    const int tid = threadIdx.x;
    const int bx = blockIdx.x, by = blockIdx.y;

    // ---- S1: fused level-1 + level-2 DWT (400 threads) ----
    if (tid < 400) {
        int ap = tid / 20, aq = tid - ap * 20;
        int gr = by * T - 8 + 4 * ap;
        int gc = bx * T - 8 + 4 * aq;
        float4 A = make_float4(0.f, 0.f, 0.f, 0.f), B = A, C = A, D = A;
        if ((unsigned)gr < NN && (unsigned)gc < NN) {
            const float* p = x + (size_t)gr * NN + gc;
            A = *reinterpret_cast<const float4*>(p);
            B = *reinterpret_cast<const float4*>(p + NN);
            C = *reinterpret_cast<const float4*>(p + 2 * NN);
            D = *reinterpret_cast<const float4*>(p + 3 * NN);
        }
        float ll00 = (A.x + A.y + B.x + B.y) * 0.5f;
        float lh00 = (A.x + A.y - B.x - B.y) * 0.5f;
        float hl00 = (A.x - A.y + B.x - B.y) * 0.5f;
        float hh00 = (A.x - A.y - B.x + B.y) * 0.5f;
        float ll01 = (A.z + A.w + B.z + B.w) * 0.5f;
        float lh01 = (A.z + A.w - B.z - B.w) * 0.5f;
        float hl01 = (A.z - A.w + B.z - B.w) * 0.5f;
        float hh01 = (A.z - A.w - B.z + B.w) * 0.5f;
        float ll10 = (C.x + C.y + D.x + D.y) * 0.5f;
        float lh10 = (C.x + C.y - D.x - D.y) * 0.5f;
        float hl10 = (C.x - C.y + D.x - D.y) * 0.5f;
        float hh10 = (C.x - C.y - D.x + D.y) * 0.5f;
        float ll11 = (C.z + C.w + D.z + D.w) * 0.5f;
        float lh11 = (C.z + C.w - D.z - D.w) * 0.5f;
        float hl11 = (C.z - C.w + D.z - D.w) * 0.5f;
        float hh11 = (C.z - C.w - D.z + D.w) * 0.5f;

        int r0 = (2 * ap) * ST1 + 2 * aq;
        int r1 = r0 + ST1;
        *reinterpret_cast<float2*>(&s[O_LH1 + r0]) = make_float2(lh00, lh01);
        *reinterpret_cast<float2*>(&s[O_LH1 + r1]) = make_float2(lh10, lh11);
        *reinterpret_cast<float2*>(&s[O_HL1 + r0]) = make_float2(hl00, hl01);
        *reinterpret_cast<float2*>(&s[O_HL1 + r1]) = make_float2(hl10, hl11);
        s[O_HH1 + r0 + 1] = hh00;
        s[O_HH1 + r0 + 2] = hh01;
        s[O_HH1 + r1 + 1] = hh10;
        s[O_HH1 + r1 + 2] = hh11;

        s[O_LL2 + tid] = (ll00 + ll01 + ll10 + ll11) * 0.5f;
        s[O_LH2 + tid] = (ll00 + ll01 - ll10 - ll11) * 0.5f;
        s[O_HL2 + tid] = (ll00 - ll01 + ll10 - ll11) * 0.5f;
        s[O_HH2 + tid] = (ll00 - ll01 - ll10 + ll11) * 0.5f;
    }
    __syncthreads();

    // ---- S2 (one phase, disjoint warp ranges):
    //  tid 0-255:   conv7 -> CHH1, 2 cols x 2 rows, f32x2.
    //  tid 256-319: conv5 -> CHH2, 2 cols x 2 rows, f32x2.
    //  tid 320-447: lvl3 DWT, bar.sync(1,128), then IDWT3+conv3 -> REC2.
    if (tid < 256) {
        int r = tid >> 4;          // 0..15 -> output rows 2r, 2r+1
        int c = tid & 15;          // output cols 2c, 2c+1
        float bv = CB7;
        ull acc0 = pk2(bv, bv), acc1 = acc0;
#pragma unroll
        for (int u = 0; u < 8; u++) {
            const ull* rowq = reinterpret_cast<const ull*>(
                &s[O_HH1 + (2 * r + 1 + u) * ST1 + 2 * c + 2]);
            ull e0 = rowq[0], e1 = rowq[1], e2 = rowq[2], e3 = rowq[3];
            float a1x, a1y, a3x, a3y, a5x, a5y, dump0, dump1;
            upk2(e0, dump0, a1x);
            upk2(e1, a1y, a3x);
            upk2(e2, a3y, a5x);
            upk2(e3, a5y, dump1);
            ull xp[7];
            xp[0] = e0;
            xp[1] = pk2(a1x, a1y);
            xp[2] = e1;
            xp[3] = pk2(a3x, a3y);
            xp[4] = e2;
            xp[5] = pk2(a5x, a5y);
            xp[6] = e3;
            if (u < 7) {
#pragma unroll
                for (int v = 0; v < 7; v++) acc0 = fma2(xp[v], w7p(u * 7 + v), acc0);
            }
            if (u >= 1) {
#pragma unroll
                for (int v = 0; v < 7; v++) acc1 = fma2(xp[v], w7p((u - 1) * 7 + v), acc1);
            }
        }
        float lo, hi;
        upk2(acc0, lo, hi);
        *reinterpret_cast<float2*>(&s[O_CHH1 + (2 * r) * 32 + 2 * c]) = make_float2(lo, hi);
        upk2(acc1, lo, hi);
        *reinterpret_cast<float2*>(&s[O_CHH1 + (2 * r + 1) * 32 + 2 * c]) = make_float2(lo, hi);
    } else if (tid < 320) {
        int t2 = tid - 256;
        int r = t2 >> 3;           // 0..7 -> output rows 2r, 2r+1
        int c = t2 & 7;            // output cols 2c, 2c+1
        float bv = CB5;
        ull acc0 = pk2(bv, bv), acc1 = acc0;
#pragma unroll
        for (int u = 0; u < 6; u++) {
            const ull* rowq = reinterpret_cast<const ull*>(
                &s[O_HH2 + (2 * r + u) * 20 + 2 * c]);
            ull e0 = rowq[0], e1 = rowq[1], e2 = rowq[2];
            float a1x, a1y, a3x, a3y, dump0, dump1;
            upk2(e0, dump0, a1x);
            upk2(e1, a1y, a3x);
            upk2(e2, a3y, dump1);
            ull xp[5];
            xp[0] = e0;
            xp[1] = pk2(a1x, a1y);
            xp[2] = e1;
            xp[3] = pk2(a3x, a3y);
            xp[4] = e2;
            if (u < 5) {
#pragma unroll
                for (int v = 0; v < 5; v++) acc0 = fma2(xp[v], w5p(u * 5 + v), acc0);
            }
            if (u >= 1) {
#pragma unroll
                for (int v = 0; v < 5; v++) acc1 = fma2(xp[v], w5p((u - 1) * 5 + v), acc1);
            }
        }
        float lo, hi;
        upk2(acc0, lo, hi);
        *reinterpret_cast<float2*>(&s[O_CHH2 + (2 * r) * 16 + 2 * c]) = make_float2(lo, hi);
        upk2(acc1, lo, hi);
        *reinterpret_cast<float2*>(&s[O_CHH2 + (2 * r + 1) * 16 + 2 * c]) = make_float2(lo, hi);
    } else if (tid < 448) {
        int t3 = tid - 320;
        if (t3 < 100) {
            int as = t3 / 10, at = t3 - as * 10;
            float2 t0 = *reinterpret_cast<const float2*>(&s[O_LL2 + (2 * as) * 20 + 2 * at]);
            float2 t1 = *reinterpret_cast<const float2*>(&s[O_LL2 + (2 * as + 1) * 20 + 2 * at]);
            s[O_LL3 + t3] = (t0.x + t0.y + t1.x + t1.y) * 0.5f;
            s[O_LH3 + t3] = (t0.x + t0.y - t1.x - t1.y) * 0.5f;
            s[O_HL3 + t3] = (t0.x - t0.y + t1.x - t1.y) * 0.5f;
            s[O_HH3 + t3] = (t0.x - t0.y - t1.x + t1.y) * 0.5f;
        }
        asm volatile("bar.sync 1, 128;" ::: "memory");
        if (t3 < 64) {
            int i = t3 >> 3, j = t3 & 7;
            float d = CB3;
#pragma unroll
            for (int u = 0; u < 3; u++)
#pragma unroll
                for (int v = 0; v < 3; v++)
                    d += s[O_HH3 + (i + u) * 10 + (j + v)] * W3S(u * 3 + v);
            float a = s[O_LL3 + (i + 1) * 10 + (j + 1)];
            float b = s[O_LH3 + (i + 1) * 10 + (j + 1)];
            float c = s[O_HL3 + (i + 1) * 10 + (j + 1)];
            *reinterpret_cast<float2*>(&s[O_REC2 + (2 * i) * 16 + 2 * j]) =
                make_float2((a + b + c + d) * 0.5f, (a + b - c - d) * 0.5f);
            *reinterpret_cast<float2*>(&s[O_REC2 + (2 * i + 1) * 16 + 2 * j]) =
                make_float2((a - b + c - d) * 0.5f, (a - b - c + d) * 0.5f);
        }
    }
    __syncthreads();

    // ---- S3: fused IDWT2 + IDWT1 -> global. All 512 threads, one output
    //      row-pair (2x4 pixels) each. ----
    {
        int i = tid >> 4;          // rec1 row 0..31
        int q = tid & 15;          // col pair
        int p = i >> 1, k = i & 1;
        float a2 = s[O_REC2 + p * 16 + q];
        float b2 = s[O_LH2 + (p + 2) * 20 + (q + 2)];
        float c2 = s[O_HL2 + (p + 2) * 20 + (q + 2)];
        float d2 = s[O_CHH2 + p * 16 + q];
        float ra, rb;
        if (k == 0) {
            ra = (a2 + b2 + c2 + d2) * 0.5f;
            rb = (a2 + b2 - c2 - d2) * 0.5f;
        } else {
            ra = (a2 - b2 + c2 - d2) * 0.5f;
            rb = (a2 - b2 - c2 + d2) * 0.5f;
        }
        float2 b = *reinterpret_cast<const float2*>(&s[O_LH1 + (i + 4) * ST1 + 2 * q + 4]);
        float2 c = *reinterpret_cast<const float2*>(&s[O_HL1 + (i + 4) * ST1 + 2 * q + 4]);
        float2 d = *reinterpret_cast<const float2*>(&s[O_CHH1 + i * 32 + 2 * q]);
        float4 e0, e1;
        e0.x = (ra + b.x + c.x + d.x) * 0.5f;
        e0.y = (ra + b.x - c.x - d.x) * 0.5f;
        e0.z = (rb + b.y + c.y + d.y) * 0.5f;
        e0.w = (rb + b.y - c.y - d.y) * 0.5f;
        e1.x = (ra - b.x + c.x - d.x) * 0.5f;
        e1.y = (ra - b.x - c.x + d.x) * 0.5f;
        e1.z = (rb - b.y + c.y - d.y) * 0.5f;
        e1.w = (rb - b.y - c.y + d.y) * 0.5f;
        int gr = by * T + 2 * i;
        int gc = bx * T + 4 * q;
        *reinterpret_cast<float4*>(out + (size_t)gr * NN + gc)       = e0;
        *reinterpret_cast<float4*>(out + (size_t)(gr + 1) * NN + gc) = e1;
    }
}

extern "C" void kernel_launch(void* const* d_in, const int* in_sizes, int n_in,
                              void* d_out, int out_size)
{
    const float* x = (const float*)d_in[0];
    float* out = (float*)d_out;

    // Pack weights directly into constant storage: 2 graph nodes total.
    void* caddr = nullptr;
    cudaGetSymbolAddress(&caddr, c_w2);
    pack_weights<<<1, 192>>>((float*)caddr,
                             (const float*)d_in[1], (const float*)d_in[2],
                             (const float*)d_in[3], (const float*)d_in[4],
                             (const float*)d_in[5], (const float*)d_in[6]);

    dim3 grid(NN / T, NN / T);
    fused_wavelet_kernel<<<grid, 512>>>(x, out);
}

// round 13
// speedup vs baseline: 1.0626x; 1.0626x over previous
#include <cuda_runtime.h>

#define NN  4096
#define ST1 42   // lvl1 array col stride

// 32x64 output tile. lvl1 arrays 24 rows x 42 (stored row = logical+4;
// LH/HL stored col = logical+4, HH stored col = logical+5).
#define O_LH1  0        // 24x42 = 1008
#define O_HL1  1008
#define O_HH1  2016
#define O_LL2  3024     // 12x20, stored = logical+2
#define O_LH2  3264
#define O_HL2  3504
#define O_HH2  3744
#define O_LL3  3984     // 6x10, stored = logical+1
#define O_LH3  4044
#define O_HL3  4104
#define O_HH3  4164
#define O_CHH2 4224     // 8x16
#define O_CHH1 4352     // 16x32
#define O_REC2 4864     // 8x16
#define SMEM_FLOATS 4992

// Constant bank as float2 pairs (8B aligned for LDC.64):
//  slots 0..48  : (w7[i], w7[i]);  slots 49..73 : (w5[i], w5[i])
//  floats 148-150: b7, b5, b3;     floats 152-160: w3[0..8]
__constant__ float2 c_w2[82];

#define CW_F   ((const float*)c_w2)
#define CB7    CW_F[148]
#define CB5    CW_F[149]
#define CB3    CW_F[150]
#define W3S(i) CW_F[152 + (i)]

typedef unsigned long long ull;

__device__ __forceinline__ ull pk2(float lo, float hi) {
    ull r; asm("mov.b64 %0, {%1,%2};" : "=l"(r) : "f"(lo), "f"(hi)); return r;
}
__device__ __forceinline__ void upk2(ull v, float& lo, float& hi) {
    asm("mov.b64 {%0,%1}, %2;" : "=f"(lo), "=f"(hi) : "l"(v));
}
__device__ __forceinline__ ull fma2(ull a, ull b, ull c) {
    ull d; asm("fma.rn.f32x2 %0, %1, %2, %3;" : "=l"(d) : "l"(a), "l"(b), "l"(c));
    return d;
}
__device__ __forceinline__ ull w7p(int i) {
    return reinterpret_cast<const ull*>(c_w2)[i];
}
__device__ __forceinline__ ull w5p(int i) {
    return reinterpret_cast<const ull*>(c_w2)[49 + i];
}

__global__ void pack_weights(float* __restrict__ dst,
                             const float* __restrict__ w3, const float* __restrict__ b3,
                             const float* __restrict__ w5, const float* __restrict__ b5,
                             const float* __restrict__ w7, const float* __restrict__ b7)
{
    int t = threadIdx.x;
    float v = 0.f;
    if (t < 98)        v = w7[t >> 1];
    else if (t < 148)  v = w5[(t - 98) >> 1];
    else if (t == 148) v = b7[0];
    else if (t == 149) v = b5[0];
    else if (t == 150) v = b3[0];
    else if (t >= 152 && t < 161) v = w3[t - 152];
    if (t < 164) dst[t] = v;
}

__global__ __launch_bounds__(256, 8) void fused_wavelet_kernel(
    const float* __restrict__ x, float* __restrict__ out)
{
    __shared__ float s[SMEM_FLOATS];
    const int tid = threadIdx.x;
    const int bx = blockIdx.x, by = blockIdx.y;

    // ---- S1: fused level-1 + level-2 DWT. 240 threads, one lvl2 position
    //      (= 2x2 lvl1 quads = 4x4 input pixels, 4 x float4) each. ----
    if (tid < 240) {
        int ap = tid / 20, aq = tid - ap * 20;     // lvl2 stored coords 12x20
        int gr = by * 32 - 8 + 4 * ap;
        int gc = bx * 64 - 8 + 4 * aq;
        float4 A = make_float4(0.f, 0.f, 0.f, 0.f), B = A, C = A, D = A;
        if ((unsigned)gr < NN && (unsigned)gc < NN) {
            const float* p = x + (size_t)gr * NN + gc;
            A = *reinterpret_cast<const float4*>(p);
            B = *reinterpret_cast<const float4*>(p + NN);
            C = *reinterpret_cast<const float4*>(p + 2 * NN);
            D = *reinterpret_cast<const float4*>(p + 3 * NN);
        }
        float ll00 = (A.x + A.y + B.x + B.y) * 0.5f;
        float lh00 = (A.x + A.y - B.x - B.y) * 0.5f;
        float hl00 = (A.x - A.y + B.x - B.y) * 0.5f;
        float hh00 = (A.x - A.y - B.x + B.y) * 0.5f;
        float ll01 = (A.z + A.w + B.z + B.w) * 0.5f;
        float lh01 = (A.z + A.w - B.z - B.w) * 0.5f;
        float hl01 = (A.z - A.w + B.z - B.w) * 0.5f;
        float hh01 = (A.z - A.w - B.z + B.w) * 0.5f;
        float ll10 = (C.x + C.y + D.x + D.y) * 0.5f;
        float lh10 = (C.x + C.y - D.x - D.y) * 0.5f;
        float hl10 = (C.x - C.y + D.x - D.y) * 0.5f;
        float hh10 = (C.x - C.y - D.x + D.y) * 0.5f;
        float ll11 = (C.z + C.w + D.z + D.w) * 0.5f;
        float lh11 = (C.z + C.w - D.z - D.w) * 0.5f;
        float hl11 = (C.z - C.w + D.z - D.w) * 0.5f;
        float hh11 = (C.z - C.w - D.z + D.w) * 0.5f;

        int r0 = (2 * ap) * ST1 + 2 * aq;
        int r1 = r0 + ST1;
        *reinterpret_cast<float2*>(&s[O_LH1 + r0]) = make_float2(lh00, lh01);
        *reinterpret_cast<float2*>(&s[O_LH1 + r1]) = make_float2(lh10, lh11);
        *reinterpret_cast<float2*>(&s[O_HL1 + r0]) = make_float2(hl00, hl01);
        *reinterpret_cast<float2*>(&s[O_HL1 + r1]) = make_float2(hl10, hl11);
        s[O_HH1 + r0 + 1] = hh00;
        s[O_HH1 + r0 + 2] = hh01;
        s[O_HH1 + r1 + 1] = hh10;
        s[O_HH1 + r1 + 2] = hh11;

        s[O_LL2 + tid] = (ll00 + ll01 + ll10 + ll11) * 0.5f;
        s[O_LH2 + tid] = (ll00 + ll01 - ll10 - ll11) * 0.5f;
        s[O_HL2 + tid] = (ll00 - ll01 + ll10 - ll11) * 0.5f;
        s[O_HH2 + tid] = (ll00 - ll01 - ll10 + ll11) * 0.5f;
    }
    __syncthreads();

    // ---- S2 (one phase, disjoint warp ranges):
    //  tid 0-63:    conv7 -> CHH1 (16x32), 2 cols x 4 rows, f32x2.
    //  tid 64-95:   conv5 -> CHH2 (8x16), 2 cols x 2 rows, f32x2.
    //  tid 96-159:  lvl3 DWT (60 pos), bar.sync(1,64), IDWT3+conv3 -> REC2.
    if (tid < 64) {
        int r = tid >> 4;          // 0..3 -> output rows 4r..4r+3
        int c = tid & 15;          // output cols 2c, 2c+1
        float bv = CB7;
        ull acc0 = pk2(bv, bv), acc1 = acc0, acc2 = acc0, acc3 = acc0;
#pragma unroll
        for (int u = 0; u < 10; u++) {
            const ull* rowq = reinterpret_cast<const ull*>(
                &s[O_HH1 + (4 * r + 1 + u) * ST1 + 2 * c + 2]);
            ull e0 = rowq[0], e1 = rowq[1], e2 = rowq[2], e3 = rowq[3];
            float a1x, a1y, a3x, a3y, a5x, a5y, dump0, dump1;
            upk2(e0, dump0, a1x);
            upk2(e1, a1y, a3x);
            upk2(e2, a3y, a5x);
            upk2(e3, a5y, dump1);
            ull xp[7];
            xp[0] = e0;
            xp[1] = pk2(a1x, a1y);
            xp[2] = e1;
            xp[3] = pk2(a3x, a3y);
            xp[4] = e2;
            xp[5] = pk2(a5x, a5y);
            xp[6] = e3;
#pragma unroll
            for (int k = 0; k < 4; k++) {
                int uu = u - k;
                if (uu >= 0 && uu < 7) {
                    ull a = (k == 0) ? acc0 : (k == 1) ? acc1 : (k == 2) ? acc2 : acc3;
#pragma unroll
                    for (int v = 0; v < 7; v++) a = fma2(xp[v], w7p(uu * 7 + v), a);
                    if (k == 0) acc0 = a; else if (k == 1) acc1 = a;
                    else if (k == 2) acc2 = a; else acc3 = a;
                }
            }
        }
        float lo, hi;
        upk2(acc0, lo, hi);
        *reinterpret_cast<float2*>(&s[O_CHH1 + (4 * r + 0) * 32 + 2 * c]) = make_float2(lo, hi);
        upk2(acc1, lo, hi);
        *reinterpret_cast<float2*>(&s[O_CHH1 + (4 * r + 1) * 32 + 2 * c]) = make_float2(lo, hi);
        upk2(acc2, lo, hi);
        *reinterpret_cast<float2*>(&s[O_CHH1 + (4 * r + 2) * 32 + 2 * c]) = make_float2(lo, hi);
        upk2(acc3, lo, hi);
        *reinterpret_cast<float2*>(&s[O_CHH1 + (4 * r + 3) * 32 + 2 * c]) = make_float2(lo, hi);
    } else if (tid < 96) {
        int t2 = tid - 64;
        int r = t2 >> 3;           // 0..3 -> output rows 2r, 2r+1
        int c = t2 & 7;            // output cols 2c, 2c+1
        float bv = CB5;
        ull acc0 = pk2(bv, bv), acc1 = acc0;
#pragma unroll
        for (int u = 0; u < 6; u++) {
            const ull* rowq = reinterpret_cast<const ull*>(
                &s[O_HH2 + (2 * r + u) * 20 + 2 * c]);
            ull e0 = rowq[0], e1 = rowq[1], e2 = rowq[2];
            float a1x, a1y, a3x, a3y, dump0, dump1;
            upk2(e0, dump0, a1x);
            upk2(e1, a1y, a3x);
            upk2(e2, a3y, dump1);
            ull xp[5];
            xp[0] = e0;
            xp[1] = pk2(a1x, a1y);
            xp[2] = e1;
            xp[3] = pk2(a3x, a3y);
            xp[4] = e2;
            if (u < 5) {
#pragma unroll
                for (int v = 0; v < 5; v++) acc0 = fma2(xp[v], w5p(u * 5 + v), acc0);
            }
            if (u >= 1) {
#pragma unroll
                for (int v = 0; v < 5; v++) acc1 = fma2(xp[v], w5p((u - 1) * 5 + v), acc1);
            }
        }
        float lo, hi;
        upk2(acc0, lo, hi);
        *reinterpret_cast<float2*>(&s[O_CHH2 + (2 * r) * 16 + 2 * c]) = make_float2(lo, hi);
        upk2(acc1, lo, hi);
        *reinterpret_cast<float2*>(&s[O_CHH2 + (2 * r + 1) * 16 + 2 * c]) = make_float2(lo, hi);
    } else if (tid < 160) {
        int t3 = tid - 96;
        if (t3 < 60) {
            int as = t3 / 10, at = t3 - as * 10;
            float2 t0 = *reinterpret_cast<const float2*>(&s[O_LL2 + (2 * as) * 20 + 2 * at]);
            float2 t1 = *reinterpret_cast<const float2*>(&s[O_LL2 + (2 * as + 1) * 20 + 2 * at]);
            s[O_LL3 + t3] = (t0.x + t0.y + t1.x + t1.y) * 0.5f;
            s[O_LH3 + t3] = (t0.x + t0.y - t1.x - t1.y) * 0.5f;
            s[O_HL3 + t3] = (t0.x - t0.y + t1.x - t1.y) * 0.5f;
            s[O_HH3 + t3] = (t0.x - t0.y - t1.x + t1.y) * 0.5f;
        }
        asm volatile("bar.sync 1, 64;" ::: "memory");
        if (t3 < 32) {
            int i = t3 >> 3, j = t3 & 7;       // lvl3 logical 4x8
            float d = CB3;
#pragma unroll
            for (int u = 0; u < 3; u++)
#pragma unroll
                for (int v = 0; v < 3; v++)
                    d += s[O_HH3 + (i + u) * 10 + (j + v)] * W3S(u * 3 + v);
            float a = s[O_LL3 + (i + 1) * 10 + (j + 1)];
            float b = s[O_LH3 + (i + 1) * 10 + (j + 1)];
            float c = s[O_HL3 + (i + 1) * 10 + (j + 1)];
            *reinterpret_cast<float2*>(&s[O_REC2 + (2 * i) * 16 + 2 * j]) =
                make_float2((a + b + c + d) * 0.5f, (a + b - c - d) * 0.5f);
            *reinterpret_cast<float2*>(&s[O_REC2 + (2 * i + 1) * 16 + 2 * j]) =
                make_float2((a - b + c - d) * 0.5f, (a - b - c + d) * 0.5f);
        }
    }
    __syncthreads();

    // ---- S3: fused IDWT2 + IDWT1 -> global. 256 threads, one rec1 row-pair
    //      (2x4 output pixels) each. ----
    {
        int i = tid >> 4;          // rec1 row 0..15
        int q = tid & 15;          // col pair
        int p = i >> 1, k = i & 1;
        float a2 = s[O_REC2 + p * 16 + q];
        float b2 = s[O_LH2 + (p + 2) * 20 + (q + 2)];
        float c2 = s[O_HL2 + (p + 2) * 20 + (q + 2)];
        float d2 = s[O_CHH2 + p * 16 + q];
        float ra, rb;
        if (k == 0) {
            ra = (a2 + b2 + c2 + d2) * 0.5f;
            rb = (a2 + b2 - c2 - d2) * 0.5f;
        } else {
            ra = (a2 - b2 + c2 - d2) * 0.5f;
            rb = (a2 - b2 - c2 + d2) * 0.5f;
        }
        float2 b = *reinterpret_cast<const float2*>(&s[O_LH1 + (i + 4) * ST1 + 2 * q + 4]);
        float2 c = *reinterpret_cast<const float2*>(&s[O_HL1 + (i + 4) * ST1 + 2 * q + 4]);
        float2 d = *reinterpret_cast<const float2*>(&s[O_CHH1 + i * 32 + 2 * q]);
        float4 e0, e1;
        e0.x = (ra + b.x + c.x + d.x) * 0.5f;
        e0.y = (ra + b.x - c.x - d.x) * 0.5f;
        e0.z = (rb + b.y + c.y + d.y) * 0.5f;
        e0.w = (rb + b.y - c.y - d.y) * 0.5f;
        e1.x = (ra - b.x + c.x - d.x) * 0.5f;
        e1.y = (ra - b.x - c.x + d.x) * 0.5f;
        e1.z = (rb - b.y + c.y - d.y) * 0.5f;
        e1.w = (rb - b.y - c.y + d.y) * 0.5f;
        int gr = by * 32 + 2 * i;
        int gc = bx * 64 + 4 * q;
        *reinterpret_cast<float4*>(out + (size_t)gr * NN + gc)       = e0;
        *reinterpret_cast<float4*>(out + (size_t)(gr + 1) * NN + gc) = e1;
    }
}

extern "C" void kernel_launch(void* const* d_in, const int* in_sizes, int n_in,
                              void* d_out, int out_size)
{
    const float* x = (const float*)d_in[0];
    float* out = (float*)d_out;

    // Pack weights directly into constant storage: 2 graph nodes total.
    void* caddr = nullptr;
    cudaGetSymbolAddress(&caddr, c_w2);
    pack_weights<<<1, 192>>>((float*)caddr,
                             (const float*)d_in[1], (const float*)d_in[2],
                             (const float*)d_in[3], (const float*)d_in[4],
                             (const float*)d_in[5], (const float*)d_in[6]);

    dim3 grid(NN / 64, NN / 32);
    fused_wavelet_kernel<<<grid, 256>>>(x, out);
}